// round 11
// baseline (speedup 1.0000x reference)
#include <cuda_runtime.h>
#include <math.h>
#include <stdint.h>

#define BATCH 2048

// ---------------- scratch (device globals; no allocs allowed) ----------------
__device__ __align__(16) unsigned g_bits1[BATCH * 256];   // [img][16*16] 32 ch-bits per pixel
__device__ __align__(16) unsigned g_bits2[BATCH * 128];   // [img][128] fc1-input bit words
__device__ __align__(16) unsigned long long g_w1p[32 * 27]; // sign(conv1_w) dup into f32x2
__device__ __align__(16) unsigned g_w2bp[64 * 12];        // conv2 weight bits, padded 12/oc
__device__ int      g_corr[64 * 16];                      // per-oc border correction by class
// transposed bit-weights: [chunk][output] x 4 words, coalesced across outputs
__device__ __align__(16) unsigned g_fc1bt[32 * 512 * 4];  // chunk c: words 4c..4c+3 of each o
__device__ __align__(16) unsigned g_fc2bt[4 * 256 * 4];
__device__ float g_inv1[32], g_sh1[32];
__device__ float g_inv2[64], g_sh2[64];
__device__ float g_inv3[512], g_sh3[512];
__device__ float g_inv4[256], g_sh4[256];

// bn applied EXACTLY like jax: x*inv + sh, two roundings, sh = b - m*inv
__device__ __forceinline__ float bn_apply(float x, float inv, float sh) {
    return __fadd_rn(__fmul_rn(x, inv), sh);
}

#define FMA_F32X2(d, a, b, c) \
    asm("fma.rn.f32x2 %0, %1, %2, %3;" : "=l"(d) : "l"(a), "l"(b), "l"(c))
#define ADD_F32X2(d, a, b) \
    asm("add.rn.f32x2 %0, %1, %2;" : "=l"(d) : "l"(a), "l"(b))
#define PACK_F32X2(out, lo, hi) \
    asm("mov.b64 %0, {%1, %2};" : "=l"(out) : "f"(lo), "f"(hi))
#define UNPACK_F32X2(lo, hi, in) \
    asm("mov.b64 {%0, %1}, %2;" : "=f"(lo), "=f"(hi) : "l"(in))

// ---------------- unified prep: coalesced ballot packing + tables ------------
__global__ void __launch_bounds__(256) prep_all(
        const float* __restrict__ fw1, const float* __restrict__ fw2,
        const float* __restrict__ w1, const float* __restrict__ w2,
        const float* g1, const float* b1, const float* m1, const float* v1,
        const float* g2, const float* b2, const float* m2, const float* v2,
        const float* g3, const float* b3, const float* m3, const float* v3,
        const float* g4, const float* b4, const float* m4, const float* v4) {
    int blk = blockIdx.x;
    int t = threadIdx.x;
    int wp = t >> 5, l = t & 31;

    if (blk < 8192) {                       // fc1: 65536 words
        int widx = blk * 8 + wp;
        int o = widx >> 7, q = widx & 127;
        float v = fw1[(size_t)o * 4096 + q * 32 + l];
        unsigned bal = __ballot_sync(0xffffffffu, v > 0.f);
        if (l == 0) g_fc1bt[(((q >> 2) * 512) + o) * 4 + (q & 3)] = bal;
    } else if (blk < 8704) {                // fc2: 4096 words
        int widx = (blk - 8192) * 8 + wp;
        int o = widx >> 4, q = widx & 15;
        float v = fw2[(size_t)o * 512 + q * 32 + l];
        unsigned bal = __ballot_sync(0xffffffffu, v > 0.f);
        if (l == 0) g_fc2bt[(((q >> 2) * 256) + o) * 4 + (q & 3)] = bal;
    } else if (blk == 8704) {               // conv1 weights -> f32x2 dup
        for (int i = t; i < 864; i += 256) {
            float w = w1[i];
            float s = (w > 0.f) ? 1.f : ((w < 0.f) ? -1.f : 0.f);
            unsigned long long p;
            PACK_F32X2(p, s, s);
            g_w1p[i] = p;
        }
    } else if (blk == 8705) {               // conv2 bit tables + corr table
        __shared__ unsigned sw[576];
        for (int i = t; i < 576; i += 256) {
            int oc = i / 9, tap = i % 9;
            unsigned bits = 0;
            for (int ic = 0; ic < 32; ic++)
                if (w2[oc * 288 + ic * 9 + tap] > 0.f) bits |= (1u << ic);
            sw[i] = bits;
        }
        __syncthreads();
        for (int i = t; i < 768; i += 256) {
            int oc = i / 12, j = i % 12;
            g_w2bp[i] = (j < 9) ? sw[oc * 9 + j] : 0u;
        }
        if (t < 64) {
            int T[9], R[3] = {0, 0, 0}, C[3] = {0, 0, 0};
            for (int tap = 0; tap < 9; tap++) {
                T[tap] = 32 - 2 * __popc(sw[t * 9 + tap]);
                R[tap / 3] += T[tap];
                C[tap % 3] += T[tap];
            }
            for (int cls = 0; cls < 16; cls++) {
                int corr = 0;
                if (cls < 9) {
                    int yc = cls / 3, xc = cls % 3;
                    corr = 288;
                    if (yc == 0) corr -= R[0];
                    if (yc == 2) corr -= R[2];
                    if (xc == 0) corr -= C[0];
                    if (xc == 2) corr -= C[2];
                    if (yc == 0 && xc == 0) corr += T[0];
                    if (yc == 0 && xc == 2) corr += T[2];
                    if (yc == 2 && xc == 0) corr += T[6];
                    if (yc == 2 && xc == 2) corr += T[8];
                }
                g_corr[t * 16 + cls] = corr;
            }
        }
    } else {                                // bn tables
        if (t < 32) {
            float inv = g1[t] / sqrtf(__fadd_rn(v1[t], 1e-5f));
            g_inv1[t] = inv; g_sh1[t] = __fsub_rn(b1[t], __fmul_rn(m1[t], inv));
        }
        if (t < 64) {
            float inv = g2[t] / sqrtf(__fadd_rn(v2[t], 1e-5f));
            g_inv2[t] = inv; g_sh2[t] = __fsub_rn(b2[t], __fmul_rn(m2[t], inv));
        }
        for (int i = t; i < 512; i += 256) {
            float inv = g3[i] / sqrtf(__fadd_rn(v3[i], 1e-5f));
            g_inv3[i] = inv; g_sh3[i] = __fsub_rn(b3[i], __fmul_rn(m3[i], inv));
        }
        if (t < 256) {
            float inv = g4[t] / sqrtf(__fadd_rn(v4[t], 1e-5f));
            g_inv4[t] = inv; g_sh4[t] = __fsub_rn(b4[t], __fmul_rn(m4[t], inv));
        }
    }
}

// ---------------- conv1 + maxpool + bn1 + sign -> bits1 (f32x2 packed FMA) ----
__global__ void __launch_bounds__(256) convA(const float* __restrict__ x,
                                             const float* __restrict__ cb1) {
    __shared__ float sx[3][34][34];
    __shared__ unsigned long long wp2[864];
    __shared__ float sinv[32], ssh[32], sb[32];
    int tid = threadIdx.x;
    int img = blockIdx.x;

    float* sxf = &sx[0][0][0];
    for (int i = tid; i < 3 * 34 * 34; i += 256) sxf[i] = 0.f;
    __syncthreads();
    const float* xin = x + (size_t)img * 3072;
    for (int i = tid; i < 3072; i += 256) {
        int c = i >> 10, p = i & 1023;
        sx[c][(p >> 5) + 1][(p & 31) + 1] = xin[i];
    }
    for (int i = tid; i < 864; i += 256) wp2[i] = g_w1p[i];
    if (tid < 32) { sinv[tid] = g_inv1[tid]; ssh[tid] = g_sh1[tid]; sb[tid] = cb1[tid]; }
    __syncthreads();

    int py = tid >> 4, px = tid & 15;
    unsigned long long pr[3][4][3];
#pragma unroll
    for (int c = 0; c < 3; c++)
#pragma unroll
        for (int y = 0; y < 4; y++) {
            float r0 = sx[c][2 * py + y][2 * px + 0];
            float r1 = sx[c][2 * py + y][2 * px + 1];
            float r2 = sx[c][2 * py + y][2 * px + 2];
            float r3 = sx[c][2 * py + y][2 * px + 3];
            PACK_F32X2(pr[c][y][0], r0, r1);
            PACK_F32X2(pr[c][y][1], r1, r2);
            PACK_F32X2(pr[c][y][2], r2, r3);
        }

    unsigned mask = 0;
    for (int oc = 0; oc < 32; oc++) {
        unsigned long long accA[2] = {0ull, 0ull}, accB[2] = {0ull, 0ull};
        const unsigned long long* w = &wp2[oc * 27];
#pragma unroll
        for (int c = 0; c < 3; c++)
#pragma unroll
            for (int ky = 0; ky < 3; ky++)
#pragma unroll
                for (int kx = 0; kx < 3; kx++) {
                    int t = c * 9 + ky * 3 + kx;
                    int p = t & 1;
                    unsigned long long wv = w[t];
                    FMA_F32X2(accA[p], wv, pr[c][ky][kx], accA[p]);
                    FMA_F32X2(accB[p], wv, pr[c][ky + 1][kx], accB[p]);
                }
        unsigned long long sA, sB;
        ADD_F32X2(sA, accA[0], accA[1]);
        ADD_F32X2(sB, accB[0], accB[1]);
        float a00, a01, a10, a11;
        UNPACK_F32X2(a00, a01, sA);
        UNPACK_F32X2(a10, a11, sB);
        float b = sb[oc];
        a00 = __fadd_rn(a00, b); a01 = __fadd_rn(a01, b);
        a10 = __fadd_rn(a10, b); a11 = __fadd_rn(a11, b);
        float m = fmaxf(fmaxf(a00, a01), fmaxf(a10, a11));
        float v = bn_apply(m, sinv[oc], ssh[oc]);
        if (v > 0.f) mask |= (1u << oc);
    }
    g_bits1[img * 256 + tid] = mask;
}

// ---------------- conv2 (xnor-popc) + maxpool + bn2 + sign -> bits2 ----------
__global__ void __launch_bounds__(256) convB(const float* __restrict__ cb2) {
    __shared__ unsigned tile[18][18];
    __shared__ __align__(16) unsigned w2s[768];   // 64 oc x 12 padded
    __shared__ int corr_s[1024];                  // 64 oc x 16 classes
    __shared__ float sb[64], sinv[64], ssh[64];
    int tid = threadIdx.x;
    int img = blockIdx.x;

    for (int i = tid; i < 324; i += 256) {
        int rr = i / 18, cc = i % 18;
        unsigned v = 0;
        if (rr >= 1 && rr <= 16 && cc >= 1 && cc <= 16)
            v = g_bits1[img * 256 + (rr - 1) * 16 + (cc - 1)];
        tile[rr][cc] = v;
    }
    for (int i = tid; i < 768; i += 256) w2s[i] = g_w2bp[i];
    for (int i = tid; i < 1024; i += 256) corr_s[i] = g_corr[i];
    if (tid < 64)  { sb[tid] = cb2[tid]; sinv[tid] = g_inv2[tid]; ssh[tid] = g_sh2[tid]; }
    __syncthreads();

    int wp = tid >> 5, l = tid & 31;
    int px = l & 7;
    // loop-invariant per-window border class index (Ycls*3+Xcls)
    int cls[2][2][2];
    unsigned inw[2][4][4];
#pragma unroll
    for (int h = 0; h < 2; h++) {
        int py = 4 * h + (l >> 3);
#pragma unroll
        for (int a = 0; a < 4; a++)
#pragma unroll
            for (int b = 0; b < 4; b++) inw[h][a][b] = tile[2 * py + a][2 * px + b];
#pragma unroll
        for (int a = 0; a < 2; a++)
#pragma unroll
            for (int b = 0; b < 2; b++) {
                int Y = 2 * py + a, X = 2 * px + b;
                int yc = (Y == 0) ? 0 : ((Y == 15) ? 2 : 1);
                int xc = (X == 0) ? 0 : ((X == 15) ? 2 : 1);
                cls[h][a][b] = yc * 3 + xc;
            }
    }

#pragma unroll
    for (int k = 0; k < 8; k++) {
        int oc = wp + 8 * k;
        const uint4* wv4 = (const uint4*)&w2s[oc * 12];
        uint4 q0 = wv4[0], q1 = wv4[1], q2 = wv4[2];
        unsigned wq[9] = {q0.x, q0.y, q0.z, q0.w, q1.x, q1.y, q1.z, q1.w, q2.x};
        const int* cr = &corr_s[oc * 16];
        float bb = sb[oc], iv = sinv[oc], sh = ssh[oc];
#pragma unroll
        for (int h = 0; h < 2; h++) {
            int dmax = -1000000;
#pragma unroll
            for (int a = 0; a < 2; a++)
#pragma unroll
                for (int b = 0; b < 2; b++) {
                    int s0 = 0, s1 = 0, s2 = 0;
#pragma unroll
                    for (int kx = 0; kx < 3; kx++) {
                        s0 += __popc(inw[h][a + 0][b + kx] ^ wq[0 + kx]);
                        s1 += __popc(inw[h][a + 1][b + kx] ^ wq[3 + kx]);
                        s2 += __popc(inw[h][a + 2][b + kx] ^ wq[6 + kx]);
                    }
                    int d = cr[cls[h][a][b]] - 2 * (s0 + s1 + s2);
                    dmax = max(dmax, d);
                }
            float y = __fadd_rn((float)dmax, bb);
            float v = bn_apply(y, iv, sh);
            unsigned bal = __ballot_sync(0xffffffffu, v > 0.f);
            if (l == 0) g_bits2[img * 128 + oc * 2 + h] = bal;
        }
    }
}

// ---------------- fc1+bn3+sign -> fc2+bn4+clip -> fc3 + log_softmax ----------
// block = 512 threads, 4 samples; prefetched coalesced weight stream
__global__ void __launch_bounds__(512) fcC(const float* __restrict__ fb1,
                                           const float* __restrict__ fb2,
                                           const float* __restrict__ w3,
                                           const float* __restrict__ b3,
                                           float* __restrict__ out) {
    __shared__ uint4 a2s[4][32];
    __shared__ unsigned s3[4][16];
    __shared__ float h4[4][256];
    __shared__ float w3s[2560];
    __shared__ float lg[4][10];
    int tid = threadIdx.x;
    int img0 = blockIdx.x * 4;

    if (tid < 128) {
        const uint4* src = (const uint4*)(g_bits2 + (size_t)img0 * 128);
        a2s[tid >> 5][tid & 31] = src[tid];
    }
    for (int i = tid; i < 2560; i += 512) w3s[i] = w3[i];
    __syncthreads();

    int wp = tid >> 5, l = tid & 31;

    // ---- fc1: one output per thread, 4 samples, double-buffered weights
    int cnt[4] = {0, 0, 0, 0};
    const uint4* Wt = (const uint4*)g_fc1bt;
    uint4 u = Wt[tid];
#pragma unroll 4
    for (int c = 0; c < 32; c++) {
        uint4 un;
        if (c < 31) un = Wt[(c + 1) * 512 + tid];
#pragma unroll
        for (int s = 0; s < 4; s++) {
            uint4 a = a2s[s][c];
            cnt[s] += __popc(a.x ^ u.x) + __popc(a.y ^ u.y) + __popc(a.z ^ u.z) + __popc(a.w ^ u.w);
        }
        u = un;
    }
    {
        int o = tid;
        float bb = fb1[o], iv = g_inv3[o], sh = g_sh3[o];
#pragma unroll
        for (int s = 0; s < 4; s++) {
            float hsum = __fadd_rn((float)(4096 - 2 * cnt[s]), bb);
            float v = bn_apply(hsum, iv, sh);
            unsigned bal = __ballot_sync(0xffffffffu, v > 0.f);
            if (l == 0) s3[s][wp] = bal;
        }
    }
    __syncthreads();

    // ---- fc2: 256 outputs; threads 0..255 -> samples 0,1; 256..511 -> 2,3
    {
        int o = tid & 255;
        int s0 = (tid >> 8) * 2;
        const uint4* Wt2 = (const uint4*)g_fc2bt;
        uint4 u0 = Wt2[0 * 256 + o], u1 = Wt2[1 * 256 + o];
        uint4 u2 = Wt2[2 * 256 + o], u3 = Wt2[3 * 256 + o];
        unsigned wv[16] = {u0.x, u0.y, u0.z, u0.w, u1.x, u1.y, u1.z, u1.w,
                           u2.x, u2.y, u2.z, u2.w, u3.x, u3.y, u3.z, u3.w};
        float bb = fb2[o], iv = g_inv4[o], sh = g_sh4[o];
#pragma unroll
        for (int si = 0; si < 2; si++) {
            int s = s0 + si;
            int c2 = 0;
#pragma unroll
            for (int w = 0; w < 16; w++) c2 += __popc(s3[s][w] ^ wv[w]);
            float hsum = __fadd_rn((float)(512 - 2 * c2), bb);
            float v = bn_apply(hsum, iv, sh);
            v = fminf(1.f, fmaxf(-1.f, v));
            h4[s][o] = v;
        }
    }
    __syncthreads();

    // ---- fc3 + log_softmax: warps 0..3 -> one sample each, lanes 0..9 logits
    if (wp < 4) {
        int s = wp;
        if (l < 10) {
            float acc0 = b3[l], acc1 = 0.f, acc2 = 0.f, acc3 = 0.f;
            const float* wr = &w3s[l * 256];
            for (int k = 0; k < 256; k += 4) {
                acc0 = fmaf(h4[s][k],     wr[k],     acc0);
                acc1 = fmaf(h4[s][k + 1], wr[k + 1], acc1);
                acc2 = fmaf(h4[s][k + 2], wr[k + 2], acc2);
                acc3 = fmaf(h4[s][k + 3], wr[k + 3], acc3);
            }
            lg[s][l] = (acc0 + acc1) + (acc2 + acc3);
        }
        __syncwarp();
        if (l < 10) {
            float m = -1e30f;
#pragma unroll
            for (int i = 0; i < 10; i++) m = fmaxf(m, lg[s][i]);
            float se = 0.f;
#pragma unroll
            for (int i = 0; i < 10; i++) se += expf(lg[s][i] - m);
            out[(size_t)(img0 + s) * 10 + l] = lg[s][l] - m - logf(se);
        }
    }
}

// ---------------- launch ----------------
extern "C" void kernel_launch(void* const* d_in, const int* in_sizes, int n_in,
                              void* d_out, int out_size) {
    const float* x       = (const float*)d_in[0];
    const float* conv1_w = (const float*)d_in[1];
    const float* conv1_b = (const float*)d_in[2];
    const float* bn1_g = (const float*)d_in[3];
    const float* bn1_b = (const float*)d_in[4];
    const float* bn1_m = (const float*)d_in[5];
    const float* bn1_v = (const float*)d_in[6];
    const float* conv2_w = (const float*)d_in[7];
    const float* conv2_b = (const float*)d_in[8];
    const float* bn2_g = (const float*)d_in[9];
    const float* bn2_b = (const float*)d_in[10];
    const float* bn2_m = (const float*)d_in[11];
    const float* bn2_v = (const float*)d_in[12];
    const float* fc1_w = (const float*)d_in[13];
    const float* fc1_b = (const float*)d_in[14];
    const float* bn3_g = (const float*)d_in[15];
    const float* bn3_b = (const float*)d_in[16];
    const float* bn3_m = (const float*)d_in[17];
    const float* bn3_v = (const float*)d_in[18];
    const float* fc2_w = (const float*)d_in[19];
    const float* fc2_b = (const float*)d_in[20];
    const float* bn4_g = (const float*)d_in[21];
    const float* bn4_b = (const float*)d_in[22];
    const float* bn4_m = (const float*)d_in[23];
    const float* bn4_v = (const float*)d_in[24];
    const float* fc3_w = (const float*)d_in[25];
    const float* fc3_b = (const float*)d_in[26];
    float* out = (float*)d_out;

    prep_all<<<8707, 256>>>(fc1_w, fc2_w, conv1_w, conv2_w,
                            bn1_g, bn1_b, bn1_m, bn1_v,
                            bn2_g, bn2_b, bn2_m, bn2_v,
                            bn3_g, bn3_b, bn3_m, bn3_v,
                            bn4_g, bn4_b, bn4_m, bn4_v);
    convA<<<BATCH, 256>>>(x, conv1_b);
    convB<<<BATCH, 256>>>(conv2_b);
    fcC<<<BATCH / 4, 512>>>(fc1_b, fc2_b, fc3_w, fc3_b, out);
}

// round 14
// speedup vs baseline: 1.6126x; 1.6126x over previous
#include <cuda_runtime.h>
#include <math.h>
#include <stdint.h>

#define BATCH 2048

// ---------------- scratch (device globals; no allocs allowed) ----------------
__device__ __align__(16) unsigned g_bits1[BATCH * 256];   // [img][16*16] 32 ch-bits per pixel
__device__ __align__(16) unsigned g_bits2[BATCH * 128];   // [img][128] fc1-input bit words
__device__ __align__(16) unsigned long long g_w1p[32 * 27]; // sign(conv1_w) dup into f32x2
__device__ __align__(16) unsigned g_w2bp[64 * 12];        // conv2 weight bits, padded 12/oc
__device__ int      g_w2T[64 * 9];                        // (32 - 2*popc(w)) per tap
__device__ int      g_w2R[64 * 3];                        // row sums of T
__device__ int      g_w2C[64 * 3];                        // col sums of T
// transposed bit-weights: [chunk][output] x 4 words, coalesced across outputs
__device__ __align__(16) unsigned g_fc1bt[32 * 512 * 4];  // chunk c: words 4c..4c+3 of each o
__device__ __align__(16) unsigned g_fc2bt[4 * 256 * 4];
__device__ float g_inv1[32], g_sh1[32];
__device__ float g_inv2[64], g_sh2[64];
__device__ float g_inv3[512], g_sh3[512];
__device__ float g_inv4[256], g_sh4[256];

// bn applied EXACTLY like jax: x*inv + sh, two roundings, sh = b - m*inv
__device__ __forceinline__ float bn_apply(float x, float inv, float sh) {
    return __fadd_rn(__fmul_rn(x, inv), sh);
}

#define FMA_F32X2(d, a, b, c) \
    asm("fma.rn.f32x2 %0, %1, %2, %3;" : "=l"(d) : "l"(a), "l"(b), "l"(c))
#define ADD_F32X2(d, a, b) \
    asm("add.rn.f32x2 %0, %1, %2;" : "=l"(d) : "l"(a), "l"(b))
#define PACK_F32X2(out, lo, hi) \
    asm("mov.b64 %0, {%1, %2};" : "=l"(out) : "f"(lo), "f"(hi))
#define UNPACK_F32X2(lo, hi, in) \
    asm("mov.b64 {%0, %1}, %2;" : "=f"(lo), "=f"(hi) : "l"(in))

// ---------------- unified prep: coalesced ballot packing + tables ------------
__global__ void __launch_bounds__(256) prep_all(
        const float* __restrict__ fw1, const float* __restrict__ fw2,
        const float* __restrict__ w1, const float* __restrict__ w2,
        const float* g1, const float* b1, const float* m1, const float* v1,
        const float* g2, const float* b2, const float* m2, const float* v2,
        const float* g3, const float* b3, const float* m3, const float* v3,
        const float* g4, const float* b4, const float* m4, const float* v4) {
    int blk = blockIdx.x;
    int t = threadIdx.x;
    int wp = t >> 5, l = t & 31;

    if (blk < 8192) {                       // fc1: 65536 words
        int widx = blk * 8 + wp;
        int o = widx >> 7, q = widx & 127;
        float v = fw1[(size_t)o * 4096 + q * 32 + l];
        unsigned bal = __ballot_sync(0xffffffffu, v > 0.f);
        if (l == 0) g_fc1bt[(((q >> 2) * 512) + o) * 4 + (q & 3)] = bal;
    } else if (blk < 8704) {                // fc2: 4096 words
        int widx = (blk - 8192) * 8 + wp;
        int o = widx >> 4, q = widx & 15;
        float v = fw2[(size_t)o * 512 + q * 32 + l];
        unsigned bal = __ballot_sync(0xffffffffu, v > 0.f);
        if (l == 0) g_fc2bt[(((q >> 2) * 256) + o) * 4 + (q & 3)] = bal;
    } else if (blk == 8704) {               // conv1 weights -> f32x2 dup
        for (int i = t; i < 864; i += 256) {
            float w = w1[i];
            float s = (w > 0.f) ? 1.f : ((w < 0.f) ? -1.f : 0.f);
            unsigned long long p;
            PACK_F32X2(p, s, s);
            g_w1p[i] = p;
        }
    } else if (blk == 8705) {               // conv2 bit tables (padded 12/oc)
        __shared__ unsigned sw[576];
        for (int i = t; i < 576; i += 256) {
            int oc = i / 9, tap = i % 9;
            unsigned bits = 0;
            for (int ic = 0; ic < 32; ic++)
                if (w2[oc * 288 + ic * 9 + tap] > 0.f) bits |= (1u << ic);
            sw[i] = bits;
        }
        __syncthreads();
        for (int i = t; i < 768; i += 256) {
            int oc = i / 12, j = i % 12;
            g_w2bp[i] = (j < 9) ? sw[oc * 9 + j] : 0u;
        }
        if (t < 64) {
            int R[3] = {0, 0, 0}, C[3] = {0, 0, 0};
            for (int tap = 0; tap < 9; tap++) {
                int T = 32 - 2 * __popc(sw[t * 9 + tap]);
                g_w2T[t * 9 + tap] = T;
                R[tap / 3] += T;
                C[tap % 3] += T;
            }
            for (int j = 0; j < 3; j++) { g_w2R[t * 3 + j] = R[j]; g_w2C[t * 3 + j] = C[j]; }
        }
    } else {                                // bn tables
        if (t < 32) {
            float inv = g1[t] / sqrtf(__fadd_rn(v1[t], 1e-5f));
            g_inv1[t] = inv; g_sh1[t] = __fsub_rn(b1[t], __fmul_rn(m1[t], inv));
        }
        if (t < 64) {
            float inv = g2[t] / sqrtf(__fadd_rn(v2[t], 1e-5f));
            g_inv2[t] = inv; g_sh2[t] = __fsub_rn(b2[t], __fmul_rn(m2[t], inv));
        }
        for (int i = t; i < 512; i += 256) {
            float inv = g3[i] / sqrtf(__fadd_rn(v3[i], 1e-5f));
            g_inv3[i] = inv; g_sh3[i] = __fsub_rn(b3[i], __fmul_rn(m3[i], inv));
        }
        if (t < 256) {
            float inv = g4[t] / sqrtf(__fadd_rn(v4[t], 1e-5f));
            g_inv4[t] = inv; g_sh4[t] = __fsub_rn(b4[t], __fmul_rn(m4[t], inv));
        }
    }
}

// ---------------- conv1 + maxpool + bn1 + sign -> bits1 (f32x2, 2 acc chains) --
__global__ void __launch_bounds__(256) convA(const float* __restrict__ x,
                                             const float* __restrict__ cb1) {
    __shared__ float sx[3][34][34];
    __shared__ unsigned long long wp2[864];
    __shared__ float sinv[32], ssh[32], sb[32];
    int tid = threadIdx.x;
    int img = blockIdx.x;

    float* sxf = &sx[0][0][0];
    for (int i = tid; i < 3 * 34 * 34; i += 256) sxf[i] = 0.f;
    __syncthreads();
    const float* xin = x + (size_t)img * 3072;
    for (int i = tid; i < 3072; i += 256) {
        int c = i >> 10, p = i & 1023;
        sx[c][(p >> 5) + 1][(p & 31) + 1] = xin[i];
    }
    for (int i = tid; i < 864; i += 256) wp2[i] = g_w1p[i];
    if (tid < 32) { sinv[tid] = g_inv1[tid]; ssh[tid] = g_sh1[tid]; sb[tid] = cb1[tid]; }
    __syncthreads();

    int py = tid >> 4, px = tid & 15;
    unsigned long long pr[3][4][3];
#pragma unroll
    for (int c = 0; c < 3; c++)
#pragma unroll
        for (int y = 0; y < 4; y++) {
            float r0 = sx[c][2 * py + y][2 * px + 0];
            float r1 = sx[c][2 * py + y][2 * px + 1];
            float r2 = sx[c][2 * py + y][2 * px + 2];
            float r3 = sx[c][2 * py + y][2 * px + 3];
            PACK_F32X2(pr[c][y][0], r0, r1);
            PACK_F32X2(pr[c][y][1], r1, r2);
            PACK_F32X2(pr[c][y][2], r2, r3);
        }

    unsigned mask = 0;
    for (int oc = 0; oc < 32; oc++) {
        unsigned long long accA[2] = {0ull, 0ull}, accB[2] = {0ull, 0ull};
        const unsigned long long* w = &wp2[oc * 27];
#pragma unroll
        for (int c = 0; c < 3; c++)
#pragma unroll
            for (int ky = 0; ky < 3; ky++)
#pragma unroll
                for (int kx = 0; kx < 3; kx++) {
                    int t = c * 9 + ky * 3 + kx;
                    int p = t & 1;
                    unsigned long long wv = w[t];
                    FMA_F32X2(accA[p], wv, pr[c][ky][kx], accA[p]);
                    FMA_F32X2(accB[p], wv, pr[c][ky + 1][kx], accB[p]);
                }
        unsigned long long sA, sB;
        ADD_F32X2(sA, accA[0], accA[1]);
        ADD_F32X2(sB, accB[0], accB[1]);
        float a00, a01, a10, a11;
        UNPACK_F32X2(a00, a01, sA);
        UNPACK_F32X2(a10, a11, sB);
        float b = sb[oc];
        a00 = __fadd_rn(a00, b); a01 = __fadd_rn(a01, b);
        a10 = __fadd_rn(a10, b); a11 = __fadd_rn(a11, b);
        float m = fmaxf(fmaxf(a00, a01), fmaxf(a10, a11));
        float v = bn_apply(m, sinv[oc], ssh[oc]);
        if (v > 0.f) mask |= (1u << oc);
    }
    g_bits1[img * 256 + tid] = mask;
}

// ---------------- conv2 (xnor-popc) + maxpool + bn2 + sign -> bits2 ----------
__global__ void __launch_bounds__(256) convB(const float* __restrict__ cb2) {
    __shared__ unsigned tile[18][18];
    __shared__ __align__(16) unsigned w2s[768];   // 64 oc x 12 padded
    __shared__ int Ts[576], Rs[192], Cs[192];
    __shared__ float sb[64], sinv[64], ssh[64];
    int tid = threadIdx.x;
    int img = blockIdx.x;

    for (int i = tid; i < 324; i += 256) {
        int rr = i / 18, cc = i % 18;
        unsigned v = 0;
        if (rr >= 1 && rr <= 16 && cc >= 1 && cc <= 16)
            v = g_bits1[img * 256 + (rr - 1) * 16 + (cc - 1)];
        tile[rr][cc] = v;
    }
    for (int i = tid; i < 768; i += 256) w2s[i] = g_w2bp[i];
    for (int i = tid; i < 576; i += 256) Ts[i] = g_w2T[i];
    if (tid < 192) { Rs[tid] = g_w2R[tid]; Cs[tid] = g_w2C[tid]; }
    if (tid < 64)  { sb[tid] = cb2[tid]; sinv[tid] = g_inv2[tid]; ssh[tid] = g_sh2[tid]; }
    __syncthreads();

    int wp = tid >> 5, l = tid & 31;
    unsigned inw[2][4][4];
#pragma unroll
    for (int h = 0; h < 2; h++) {
        int py = 4 * h + (l >> 3), px = l & 7;
#pragma unroll
        for (int a = 0; a < 4; a++)
#pragma unroll
            for (int b = 0; b < 4; b++) inw[h][a][b] = tile[2 * py + a][2 * px + b];
    }

#pragma unroll
    for (int k = 0; k < 8; k++) {
        int oc = wp + 8 * k;
        const uint4* wv4 = (const uint4*)&w2s[oc * 12];
        uint4 q0 = wv4[0], q1 = wv4[1], q2 = wv4[2];
        unsigned wq[9] = {q0.x, q0.y, q0.z, q0.w, q1.x, q1.y, q1.z, q1.w, q2.x};
        int R0 = Rs[oc * 3 + 0], R2 = Rs[oc * 3 + 2];
        int C0 = Cs[oc * 3 + 0], C2 = Cs[oc * 3 + 2];
        float bb = sb[oc], iv = sinv[oc], sh = ssh[oc];
#pragma unroll
        for (int h = 0; h < 2; h++) {
            int py = 4 * h + (l >> 3), px = l & 7;
            int dmax = -1000000;
#pragma unroll
            for (int a = 0; a < 2; a++)
#pragma unroll
                for (int b = 0; b < 2; b++) {
                    int s0 = 0, s1 = 0, s2 = 0;   // 3 independent chains
#pragma unroll
                    for (int kx = 0; kx < 3; kx++) {
                        s0 += __popc(inw[h][a + 0][b + kx] ^ wq[0 + kx]);
                        s1 += __popc(inw[h][a + 1][b + kx] ^ wq[3 + kx]);
                        s2 += __popc(inw[h][a + 2][b + kx] ^ wq[6 + kx]);
                    }
                    int S = s0 + s1 + s2;
                    int d = 288 - 2 * S;
                    int Y = 2 * py + a, X = 2 * px + b;
                    if (Y == 0)  d -= R0;
                    if (Y == 15) d -= R2;
                    if (X == 0)  d -= C0;
                    if (X == 15) d -= C2;
                    if (Y == 0  && X == 0)  d += Ts[oc * 9 + 0];
                    if (Y == 0  && X == 15) d += Ts[oc * 9 + 2];
                    if (Y == 15 && X == 0)  d += Ts[oc * 9 + 6];
                    if (Y == 15 && X == 15) d += Ts[oc * 9 + 8];
                    dmax = max(dmax, d);
                }
            float y = __fadd_rn((float)dmax, bb);
            float v = bn_apply(y, iv, sh);
            unsigned bal = __ballot_sync(0xffffffffu, v > 0.f);
            if (l == 0) g_bits2[img * 128 + oc * 2 + h] = bal;
        }
    }
}

// ---------------- fc1+bn3+sign -> fc2+bn4+clip -> fc3 + log_softmax ----------
// block = 512 threads, 4 samples (grid 512); plain weight stream (no predication)
__global__ void __launch_bounds__(512) fcC(const float* __restrict__ fb1,
                                           const float* __restrict__ fb2,
                                           const float* __restrict__ w3,
                                           const float* __restrict__ b3,
                                           float* __restrict__ out) {
    __shared__ uint4 a2s[4][32];
    __shared__ unsigned s3[4][16];
    __shared__ float h4[4][256];
    __shared__ float w3s[2560];
    __shared__ float lg[4][10];
    int tid = threadIdx.x;
    int img0 = blockIdx.x * 4;

    if (tid < 128) {
        const uint4* src = (const uint4*)(g_bits2 + (size_t)img0 * 128);
        a2s[tid >> 5][tid & 31] = src[tid];
    }
    for (int i = tid; i < 2560; i += 512) w3s[i] = w3[i];

    // hoist per-output scalars before the sync so LDGs drain under the ALU stream
    float bb1 = fb1[tid], iv3 = g_inv3[tid], sh3 = g_sh3[tid];
    __syncthreads();

    int wp = tid >> 5, l = tid & 31;

    // ---- fc1: one output per thread (o = tid), 4 samples, coalesced weights
    int cnt[4] = {0, 0, 0, 0};
    const uint4* Wt = (const uint4*)g_fc1bt;
    for (int c = 0; c < 32; c++) {
        uint4 u = Wt[c * 512 + tid];
#pragma unroll
        for (int s = 0; s < 4; s++) {
            uint4 a = a2s[s][c];
            cnt[s] += __popc(a.x ^ u.x) + __popc(a.y ^ u.y) + __popc(a.z ^ u.z) + __popc(a.w ^ u.w);
        }
    }
    {
#pragma unroll
        for (int s = 0; s < 4; s++) {
            float hsum = __fadd_rn((float)(4096 - 2 * cnt[s]), bb1);
            float v = bn_apply(hsum, iv3, sh3);
            unsigned bal = __ballot_sync(0xffffffffu, v > 0.f);
            if (l == 0) s3[s][wp] = bal;
        }
    }
    __syncthreads();

    // ---- fc2: 256 outputs; threads 0..255 -> samples 0,1; 256..511 -> 2,3
    {
        int o = tid & 255;
        int s0 = (tid >> 8) * 2;
        const uint4* Wt2 = (const uint4*)g_fc2bt;
        uint4 u0 = Wt2[0 * 256 + o], u1 = Wt2[1 * 256 + o];
        uint4 u2 = Wt2[2 * 256 + o], u3 = Wt2[3 * 256 + o];
        unsigned wv[16] = {u0.x, u0.y, u0.z, u0.w, u1.x, u1.y, u1.z, u1.w,
                           u2.x, u2.y, u2.z, u2.w, u3.x, u3.y, u3.z, u3.w};
        float bb = fb2[o], iv = g_inv4[o], sh = g_sh4[o];
#pragma unroll
        for (int si = 0; si < 2; si++) {
            int s = s0 + si;
            int c2 = 0;
#pragma unroll
            for (int w = 0; w < 16; w++) c2 += __popc(s3[s][w] ^ wv[w]);
            float hsum = __fadd_rn((float)(512 - 2 * c2), bb);
            float v = bn_apply(hsum, iv, sh);
            v = fminf(1.f, fmaxf(-1.f, v));
            h4[s][o] = v;
        }
    }
    __syncthreads();

    // ---- fc3 + log_softmax: warps 0..3 -> one sample each, lanes 0..9 logits
    if (wp < 4) {
        int s = wp;
        if (l < 10) {
            float acc0 = b3[l], acc1 = 0.f, acc2 = 0.f, acc3 = 0.f;
            const float* wr = &w3s[l * 256];
            for (int k = 0; k < 256; k += 4) {
                acc0 = fmaf(h4[s][k],     wr[k],     acc0);
                acc1 = fmaf(h4[s][k + 1], wr[k + 1], acc1);
                acc2 = fmaf(h4[s][k + 2], wr[k + 2], acc2);
                acc3 = fmaf(h4[s][k + 3], wr[k + 3], acc3);
            }
            lg[s][l] = (acc0 + acc1) + (acc2 + acc3);
        }
        __syncwarp();
        if (l < 10) {
            float m = -1e30f;
#pragma unroll
            for (int i = 0; i < 10; i++) m = fmaxf(m, lg[s][i]);
            float se = 0.f;
#pragma unroll
            for (int i = 0; i < 10; i++) se += expf(lg[s][i] - m);
            out[(size_t)(img0 + s) * 10 + l] = lg[s][l] - m - logf(se);
        }
    }
}

// ---------------- launch ----------------
extern "C" void kernel_launch(void* const* d_in, const int* in_sizes, int n_in,
                              void* d_out, int out_size) {
    const float* x       = (const float*)d_in[0];
    const float* conv1_w = (const float*)d_in[1];
    const float* conv1_b = (const float*)d_in[2];
    const float* bn1_g = (const float*)d_in[3];
    const float* bn1_b = (const float*)d_in[4];
    const float* bn1_m = (const float*)d_in[5];
    const float* bn1_v = (const float*)d_in[6];
    const float* conv2_w = (const float*)d_in[7];
    const float* conv2_b = (const float*)d_in[8];
    const float* bn2_g = (const float*)d_in[9];
    const float* bn2_b = (const float*)d_in[10];
    const float* bn2_m = (const float*)d_in[11];
    const float* bn2_v = (const float*)d_in[12];
    const float* fc1_w = (const float*)d_in[13];
    const float* fc1_b = (const float*)d_in[14];
    const float* bn3_g = (const float*)d_in[15];
    const float* bn3_b = (const float*)d_in[16];
    const float* bn3_m = (const float*)d_in[17];
    const float* bn3_v = (const float*)d_in[18];
    const float* fc2_w = (const float*)d_in[19];
    const float* fc2_b = (const float*)d_in[20];
    const float* bn4_g = (const float*)d_in[21];
    const float* bn4_b = (const float*)d_in[22];
    const float* bn4_m = (const float*)d_in[23];
    const float* bn4_v = (const float*)d_in[24];
    const float* fc3_w = (const float*)d_in[25];
    const float* fc3_b = (const float*)d_in[26];
    float* out = (float*)d_out;

    prep_all<<<8707, 256>>>(fc1_w, fc2_w, conv1_w, conv2_w,
                            bn1_g, bn1_b, bn1_m, bn1_v,
                            bn2_g, bn2_b, bn2_m, bn2_v,
                            bn3_g, bn3_b, bn3_m, bn3_v,
                            bn4_g, bn4_b, bn4_m, bn4_v);
    convA<<<BATCH, 256>>>(x, conv1_b);
    convB<<<BATCH, 256>>>(conv2_b);
    fcC<<<BATCH / 4, 512>>>(fc1_b, fc2_b, fc3_w, fc3_b, out);
}